// round 7
// baseline (speedup 1.0000x reference)
#include <cuda_runtime.h>

#define N_NODES 50000
#define N_EDGES 800000
#define D 96
#define WS 100                  // padded weight stride
#define SCAN_T 1024
#define SCAN_B ((N_NODES + SCAN_T - 1) / SCAN_T)   // 49

typedef unsigned long long u64;

__device__ __align__(16) float g_agg[N_NODES * D];   // gathered mean features
__device__ __align__(16) float g_h[N_NODES * D];     // layer-1 activations
__device__ int g_deg[N_NODES];
__device__ int g_off[N_NODES + 1];
__device__ int g_cur[N_NODES];
__device__ int g_src[N_EDGES];                        // CSR: src ids grouped by dst
__device__ int g_part[SCAN_B];                        // per-block partial sums
__device__ int g_is64;                                // 1 if edge_index is int64

__device__ __forceinline__ u64 pack2(float lo, float hi) {
    u64 r; asm("mov.b64 %0, {%1, %2};" : "=l"(r) : "f"(lo), "f"(hi)); return r;
}
__device__ __forceinline__ void unpack2(u64 v, float& lo, float& hi) {
    asm("mov.b64 {%0, %1}, %2;" : "=f"(lo), "=f"(hi) : "l"(v));
}
__device__ __forceinline__ void fma2(u64& d, u64 a, u64 b) {
    asm("fma.rn.f32x2 %0, %1, %2, %0;" : "+l"(d) : "l"(a), "l"(b));
}

// ---------------------------------------------------------------------------
// Zero degrees; block 0 additionally detects edge_index element width.
// ---------------------------------------------------------------------------
__global__ void zero_detect_kernel(const int* __restrict__ w) {
    int i = blockIdx.x * blockDim.x + threadIdx.x;
    if (i < N_NODES) g_deg[i] = 0;
    if (blockIdx.x == 0 && threadIdx.x < 64) {
        int t = threadIdx.x;
        int bad = (w[2 * t + 1] != 0) ? 1 : 0;
        unsigned m0 = __ballot_sync(0xffffffffu, bad);
        __shared__ unsigned s[2];
        s[t >> 5] = m0;
        __syncwarp();
        if (t == 0) {
            __threadfence_block();
            g_is64 = (s[0] | s[1]) ? 0 : 1;
        }
    }
}

__device__ __forceinline__ int load_idx(const void* eiv, int pos) {
    int v;
    if (g_is64) v = (int)((const long long*)eiv)[pos];
    else        v = ((const int*)eiv)[pos];
    return min(max(v, 0), N_NODES - 1);     // safety clamp (no-op when correct)
}

// hist: 2 edges per thread
__global__ void hist_kernel(const void* __restrict__ eiv) {
    int e = 2 * (blockIdx.x * blockDim.x + threadIdx.x);
    if (e + 1 < N_EDGES) {
        int d0, d1;
        if (g_is64) {
            const long long* p = (const long long*)eiv + N_EDGES + e;
            d0 = (int)p[0]; d1 = (int)p[1];
        } else {
            const int* p = (const int*)eiv + N_EDGES + e;
            d0 = p[0]; d1 = p[1];
        }
        d0 = min(max(d0, 0), N_NODES - 1);
        d1 = min(max(d1, 0), N_NODES - 1);
        atomicAdd(&g_deg[d0], 1);
        atomicAdd(&g_deg[d1], 1);
    } else if (e < N_EDGES) {
        atomicAdd(&g_deg[load_idx(eiv, N_EDGES + e)], 1);
    }
}

// Phase 1: per-block sums of degree chunks
__global__ __launch_bounds__(SCAN_T) void scan1_kernel() {
    __shared__ int wsum[32];
    int i = blockIdx.x * SCAN_T + threadIdx.x;
    int v = (i < N_NODES) ? g_deg[i] : 0;
    int s = v;
#pragma unroll
    for (int o = 1; o < 32; o <<= 1) s += __shfl_xor_sync(0xffffffffu, s, o);
    if ((threadIdx.x & 31) == 0) wsum[threadIdx.x >> 5] = s;
    __syncthreads();
    if (threadIdx.x < 32) {
        int t = wsum[threadIdx.x];
#pragma unroll
        for (int o = 1; o < 32; o <<= 1) t += __shfl_xor_sync(0xffffffffu, t, o);
        if (threadIdx.x == 0) g_part[blockIdx.x] = t;
    }
}

// Phase 2+3 fused: redundant partial scan + block-local scan; zero g_cur.
__global__ __launch_bounds__(SCAN_T) void scan3_kernel() {
    __shared__ int wsum[32];
    __shared__ int base_excl[SCAN_B];

    if (threadIdx.x < 64) {
        int t = threadIdx.x;
        int v = (t < SCAN_B) ? g_part[t] : 0;
        int s = v;
#pragma unroll
        for (int o = 1; o < 32; o <<= 1) {
            int u = __shfl_up_sync(0xffffffffu, s, o);
            if ((t & 31) >= o) s += u;
        }
        __shared__ int w0sum;
        if (t == 31) w0sum = s;
        __syncwarp();
        if (t >= 32) s += w0sum;
        if (t < SCAN_B) base_excl[t] = s - v;
    }
    __syncthreads();

    int i = blockIdx.x * SCAN_T + threadIdx.x;
    int v = (i < N_NODES) ? g_deg[i] : 0;
    int s = v;
#pragma unroll
    for (int o = 1; o < 32; o <<= 1) {
        int u = __shfl_up_sync(0xffffffffu, s, o);
        if ((threadIdx.x & 31) >= o) s += u;
    }
    if ((threadIdx.x & 31) == 31) wsum[threadIdx.x >> 5] = s;
    __syncthreads();
    if (threadIdx.x < 32) {
        int t = wsum[threadIdx.x];
#pragma unroll
        for (int o = 1; o < 32; o <<= 1) {
            int u = __shfl_up_sync(0xffffffffu, t, o);
            if (threadIdx.x >= o) t += u;
        }
        wsum[threadIdx.x] = t;
    }
    __syncthreads();
    int warp = threadIdx.x >> 5;
    int base = base_excl[blockIdx.x] + (warp ? wsum[warp - 1] : 0);
    int excl = base + s - v;
    if (i < N_NODES) {
        g_off[i] = excl;
        g_cur[i] = 0;
        if (i == N_NODES - 1) g_off[N_NODES] = excl + v;
    }
}

__global__ void place_kernel(const void* __restrict__ eiv) {
    int e = blockIdx.x * blockDim.x + threadIdx.x;
    if (e < N_EDGES) {
        int src = load_idx(eiv, e);
        int dst = load_idx(eiv, N_EDGES + e);
        int pos = g_off[dst] + atomicAdd(&g_cur[dst], 1);
        if (pos >= 0 && pos < N_EDGES) g_src[pos] = src;
    }
}

// ---------------------------------------------------------------------------
// Gather mean: one warp per node; 24 active lanes, one float4 per lane per
// edge (1 LDG.128 covers the whole 384B row across the warp). 4-edge unroll.
// ---------------------------------------------------------------------------
__global__ __launch_bounds__(256) void gather_kernel(const float* __restrict__ x,
                                                     int from_h) {
    int warp = (blockIdx.x * blockDim.x + threadIdx.x) >> 5;
    int lane = threadIdx.x & 31;
    if (warp >= N_NODES) return;
    const float* feat = from_h ? (const float*)g_h : x;
    int beg = g_off[warp];
    int end = g_off[warp + 1];
    bool act = lane < 24;
    float4 a = make_float4(0.f, 0.f, 0.f, 0.f);
    float4 b = make_float4(0.f, 0.f, 0.f, 0.f);
    int i = beg;
    for (; i + 3 < end; i += 4) {
        int s0 = g_src[i], s1 = g_src[i + 1], s2 = g_src[i + 2], s3 = g_src[i + 3];
        if (act) {
            float4 v0 = ((const float4*)(feat + (size_t)s0 * D))[lane];
            float4 v1 = ((const float4*)(feat + (size_t)s1 * D))[lane];
            float4 v2 = ((const float4*)(feat + (size_t)s2 * D))[lane];
            float4 v3 = ((const float4*)(feat + (size_t)s3 * D))[lane];
            a.x += v0.x + v1.x; a.y += v0.y + v1.y;
            a.z += v0.z + v1.z; a.w += v0.w + v1.w;
            b.x += v2.x + v3.x; b.y += v2.y + v3.y;
            b.z += v2.z + v3.z; b.w += v2.w + v3.w;
        }
    }
    for (; i < end; i++) {
        int s0 = g_src[i];
        if (act) {
            float4 v0 = ((const float4*)(feat + (size_t)s0 * D))[lane];
            a.x += v0.x; a.y += v0.y; a.z += v0.z; a.w += v0.w;
        }
    }
    if (act) {
        float inv = 1.0f / (float)max(end - beg, 1);
        float4 r;
        r.x = (a.x + b.x) * inv;
        r.y = (a.y + b.y) * inv;
        r.z = (a.z + b.z) * inv;
        r.w = (a.w + b.w) * inv;
        ((float4*)(g_agg + (size_t)warp * D))[lane] = r;
    }
}

// ---------------------------------------------------------------------------
// gemmR: dst[n] = feat[n] @ W^T + bias        (one thread per node)
// ---------------------------------------------------------------------------
__global__ __launch_bounds__(128) void gemmR_kernel(
    const float* __restrict__ x, int in_h,
    const float* __restrict__ W,
    const float* __restrict__ bias,
    float* __restrict__ out, int out_h)
{
    __shared__ __align__(16) float ws[D * WS];
    __shared__ float bsm[D];

    const float* feat = in_h ? (const float*)g_h : x;
    float* dst = out_h ? (float*)g_h : out;

    for (int i = threadIdx.x; i < D * D; i += 128) {
        int o = i / D, k = i % D;
        ws[k * WS + o] = W[i];
    }
    if (threadIdx.x < D) bsm[threadIdx.x] = bias[threadIdx.x];
    __syncthreads();

    int node = blockIdx.x * 128 + threadIdx.x;
    if (node >= N_NODES) return;

    u64 acc[48];
#pragma unroll
    for (int j = 0; j < 48; j++) acc[j] = pack2(bsm[2 * j], bsm[2 * j + 1]);

    const float4* f4 = (const float4*)(feat + (size_t)node * D);
#pragma unroll 1
    for (int kb = 0; kb < D / 4; kb++) {
        float4 fv = f4[kb];
        const ulonglong2* w0 = (const ulonglong2*)(ws + (4 * kb + 0) * WS);
        const ulonglong2* w1 = (const ulonglong2*)(ws + (4 * kb + 1) * WS);
        const ulonglong2* w2 = (const ulonglong2*)(ws + (4 * kb + 2) * WS);
        const ulonglong2* w3 = (const ulonglong2*)(ws + (4 * kb + 3) * WS);
        u64 ax = pack2(fv.x, fv.x);
        u64 ay = pack2(fv.y, fv.y);
        u64 az = pack2(fv.z, fv.z);
        u64 aw = pack2(fv.w, fv.w);
#pragma unroll
        for (int j = 0; j < 24; j++) {
            ulonglong2 w = w0[j];
            fma2(acc[2 * j], ax, w.x); fma2(acc[2 * j + 1], ax, w.y);
        }
#pragma unroll
        for (int j = 0; j < 24; j++) {
            ulonglong2 w = w1[j];
            fma2(acc[2 * j], ay, w.x); fma2(acc[2 * j + 1], ay, w.y);
        }
#pragma unroll
        for (int j = 0; j < 24; j++) {
            ulonglong2 w = w2[j];
            fma2(acc[2 * j], az, w.x); fma2(acc[2 * j + 1], az, w.y);
        }
#pragma unroll
        for (int j = 0; j < 24; j++) {
            ulonglong2 w = w3[j];
            fma2(acc[2 * j], aw, w.x); fma2(acc[2 * j + 1], aw, w.y);
        }
    }

    float* o = dst + (size_t)node * D;
#pragma unroll
    for (int j = 0; j < 48; j++) {
        float lo, hi;
        unpack2(acc[j], lo, hi);
        o[2 * j] = lo; o[2 * j + 1] = hi;
    }
}

// ---------------------------------------------------------------------------
// gemmL: dst[n] += g_agg[n] @ W^T ; optional ELU   (one thread per node)
// ---------------------------------------------------------------------------
__global__ __launch_bounds__(128) void gemmL_kernel(
    const float* __restrict__ W,
    float* __restrict__ out, int out_h,
    int apply_elu)
{
    __shared__ __align__(16) float ws[D * WS];

    float* dst = out_h ? (float*)g_h : out;

    for (int i = threadIdx.x; i < D * D; i += 128) {
        int o = i / D, k = i % D;
        ws[k * WS + o] = W[i];
    }
    __syncthreads();

    int node = blockIdx.x * 128 + threadIdx.x;
    if (node >= N_NODES) return;

    u64 acc[48];
    float* o = dst + (size_t)node * D;
    const float4* o4 = (const float4*)o;
#pragma unroll
    for (int j = 0; j < 24; j++) {
        float4 v = o4[j];
        acc[2 * j]     = pack2(v.x, v.y);
        acc[2 * j + 1] = pack2(v.z, v.w);
    }

    const float4* a4 = (const float4*)(g_agg + (size_t)node * D);
#pragma unroll 1
    for (int kb = 0; kb < D / 4; kb++) {
        float4 av = a4[kb];
        const ulonglong2* w0 = (const ulonglong2*)(ws + (4 * kb + 0) * WS);
        const ulonglong2* w1 = (const ulonglong2*)(ws + (4 * kb + 1) * WS);
        const ulonglong2* w2 = (const ulonglong2*)(ws + (4 * kb + 2) * WS);
        const ulonglong2* w3 = (const ulonglong2*)(ws + (4 * kb + 3) * WS);
        u64 ax = pack2(av.x, av.x);
        u64 ay = pack2(av.y, av.y);
        u64 az = pack2(av.z, av.z);
        u64 aw = pack2(av.w, av.w);
#pragma unroll
        for (int j = 0; j < 24; j++) {
            ulonglong2 w = w0[j];
            fma2(acc[2 * j], ax, w.x); fma2(acc[2 * j + 1], ax, w.y);
        }
#pragma unroll
        for (int j = 0; j < 24; j++) {
            ulonglong2 w = w1[j];
            fma2(acc[2 * j], ay, w.x); fma2(acc[2 * j + 1], ay, w.y);
        }
#pragma unroll
        for (int j = 0; j < 24; j++) {
            ulonglong2 w = w2[j];
            fma2(acc[2 * j], az, w.x); fma2(acc[2 * j + 1], az, w.y);
        }
#pragma unroll
        for (int j = 0; j < 24; j++) {
            ulonglong2 w = w3[j];
            fma2(acc[2 * j], aw, w.x); fma2(acc[2 * j + 1], aw, w.y);
        }
    }

#pragma unroll
    for (int j = 0; j < 48; j++) {
        float lo, hi;
        unpack2(acc[j], lo, hi);
        if (apply_elu) {
            lo = lo > 0.0f ? lo : expm1f(lo);
            hi = hi > 0.0f ? hi : expm1f(hi);
        }
        o[2 * j] = lo; o[2 * j + 1] = hi;
    }
}

// ---------------------------------------------------------------------------
// Launch sequence. gemmR1 (CSR-independent) sits at slot #4 for profiling.
// ---------------------------------------------------------------------------
extern "C" void kernel_launch(void* const* d_in, const int* in_sizes, int n_in,
                              void* d_out, int out_size) {
    const float* x   = (const float*)d_in[0];
    const void*  ei  = d_in[1];
    const float* W1l = (const float*)d_in[2];
    const float* b1  = (const float*)d_in[3];
    const float* W1r = (const float*)d_in[4];
    const float* W2l = (const float*)d_in[5];
    const float* b2  = (const float*)d_in[6];
    const float* W2r = (const float*)d_in[7];
    float*       out = (float*)d_out;

    const int nb = (N_NODES + 255) / 256;
    const int hb = (N_EDGES / 2 + 255) / 256;
    const int eb = (N_EDGES + 255) / 256;
    const int wb = (N_NODES * 32 + 255) / 256;
    const int gb = (N_NODES + 127) / 128;

    zero_detect_kernel<<<nb, 256>>>((const int*)ei);      // 1
    hist_kernel<<<hb, 256>>>(ei);                          // 2
    scan1_kernel<<<SCAN_B, SCAN_T>>>();                    // 3
    gemmR_kernel<<<gb, 128>>>(x, 0, W1r, b1, nullptr, 1);  // 4  g_h = x@W1r+b1
    scan3_kernel<<<SCAN_B, SCAN_T>>>();                    // 5
    place_kernel<<<eb, 256>>>(ei);                         // 6
    gather_kernel<<<wb, 256>>>(x, 0);                      // 7  g_agg = mean(x)
    gemmL_kernel<<<gb, 128>>>(W1l, nullptr, 1, 1);         // 8  g_h += agg@W1l; ELU
    gather_kernel<<<wb, 256>>>(nullptr, 1);                // 9  g_agg = mean(g_h)
    gemmR_kernel<<<gb, 128>>>(nullptr, 1, W2r, b2, out, 0);// 10 out = h@W2r+b2
    gemmL_kernel<<<gb, 128>>>(W2l, out, 0, 0);             // 11 out += agg@W2l
}